// round 12
// baseline (speedup 1.0000x reference)
#include <cuda_runtime.h>
#include <cuda_bf16.h>
#include <cuda_fp8.h>
#include <stdint.h>
#include <math.h>

typedef __nv_bfloat16 bf16;

#define NB   32
#define DIM  1024
#define EPSF 1e-12f

// Per-tensor fp8 scales: hi8 = e4m3(x*SH), lo8 = e4m3((x - bf16(x)) * SH*512)
#define SH_W  64.0f
#define SL_W  32768.0f
#define SH_X  2.0f
#define SL_X  1024.0f
#define SH_KQ 2.0f
#define SL_KQ 1024.0f
#define SH_SM 128.0f
#define SL_SM 65536.0f
// invs = 1/(SH_A*SL_B) (= 1/(SL_A*SH_B), equal by construction)
#define INVS_KQ (1.0f / 65536.0f)
#define INVS_Y  (1.0f / 2048.0f)
#define INVS_Z  (1.0f / 131072.0f)

// ---------------- scratch (__device__ globals; no allocations) ----------------
__device__ __align__(128) bf16    g_Wk_h [DIM*DIM];
__device__ __align__(128) uint8_t g_Wk_8h[DIM*DIM], g_Wk_8l[DIM*DIM];
__device__ __align__(128) bf16    g_Wq_h [DIM*DIM];
__device__ __align__(128) uint8_t g_Wq_8h[DIM*DIM], g_Wq_8l[DIM*DIM];
__device__ __align__(128) bf16    g_X_h  [NB*DIM*DIM];
__device__ __align__(128) uint8_t g_X_8h [NB*DIM*DIM], g_X_8l [NB*DIM*DIM];
__device__ __align__(128) bf16    g_XT_h [NB*DIM*DIM];
__device__ __align__(128) uint8_t g_XT_8h[NB*DIM*DIM], g_XT_8l[NB*DIM*DIM];
__device__ __align__(128) bf16    g_KT_h [NB*DIM*DIM];
__device__ __align__(128) uint8_t g_KT_8h[NB*DIM*DIM], g_KT_8l[NB*DIM*DIM];
__device__ __align__(128) bf16    g_QT_h [NB*DIM*DIM];
__device__ __align__(128) uint8_t g_QT_8h[NB*DIM*DIM], g_QT_8l[NB*DIM*DIM];
__device__ __align__(128) bf16    g_SM_h [NB*DIM*DIM];
__device__ __align__(128) uint8_t g_SM_8h[NB*DIM*DIM], g_SM_8l[NB*DIM*DIM];
__device__ __align__(128) float   g_YT[NB*DIM*DIM];
__device__ float g_partK[8*NB*DIM], g_partQ[8*NB*DIM];
__device__ float g_DK2[NB*DIM], g_DQ2[NB*DIM];

// ---------------- helpers ----------------
__device__ __forceinline__ uint32_t smem_to_u32(const void* p) {
    uint32_t a;
    asm("{ .reg .u64 t; cvta.to.shared.u64 t, %1; cvt.u32.u64 %0, t; }" : "=r"(a) : "l"(p));
    return a;
}
__device__ __forceinline__ uint8_t to_e4m3(float v) {
    return (uint8_t)__nv_cvt_float_to_fp8(v, __NV_SATFINITE, __NV_E4M3);
}

#define LDSM4(r, addr) \
    asm volatile("ldmatrix.sync.aligned.m8n8.x4.shared.b16 {%0,%1,%2,%3}, [%4];" \
        : "=r"((r)[0]), "=r"((r)[1]), "=r"((r)[2]), "=r"((r)[3]) : "r"(addr))

#define MMA(acc, a, b0, b1) \
    asm volatile("mma.sync.aligned.m16n8k16.row.col.f32.bf16.bf16.f32 " \
        "{%0,%1,%2,%3}, {%4,%5,%6,%7}, {%8,%9}, {%0,%1,%2,%3};" \
        : "+f"((acc)[0]), "+f"((acc)[1]), "+f"((acc)[2]), "+f"((acc)[3]) \
        : "r"((a)[0]), "r"((a)[1]), "r"((a)[2]), "r"((a)[3]), "r"(b0), "r"(b1))

// fp8 e4m3 x e4m3, f16 accumulator (2 regs)
#define MMA8H(d, a, b0, b1) \
    asm volatile("mma.sync.aligned.m16n8k32.row.col.f16.e4m3.e4m3.f16 " \
        "{%0,%1}, {%2,%3,%4,%5}, {%6,%7}, {%0,%1};" \
        : "+r"((d)[0]), "+r"((d)[1]) \
        : "r"((a)[0]), "r"((a)[1]), "r"((a)[2]), "r"((a)[3]), "r"(b0), "r"(b1))

// Stage: A{bf16 8K, e4m3h 4K, e4m3l 4K} + B{bf16 8K, e4m3h 4K, e4m3l 4K} = 32K
#define STAGE_BYTES 32768
#define NSTAGE 3
#define SMEM_BYTES (NSTAGE * STAGE_BYTES)   // 96 KB

// ---------------------------------------------------------------------------
// Split GEMM: D[m,n] = sum_k A[m,k]*B[n,k], K-major operands.
// CTA 128x128, 8 warps (2m x 4n), warp tile 64x32, BK=32, 3-stage cp.async.
// bf16 hi x hi -> acc (fp32); corrections Ahi8*Blo8 + Alo8*Bhi8 (scaled e4m3)
// -> acc8 (f16) at 2x rate; epilogue v = acc + f32(acc8)*invs.
// EPI 0: bf16 + scaled e4m3 hi/lo TRANSPOSED store out[n][m], +bias,
//        + exact deterministic per-CTA partial column norms.
// EPI 1: fp32 TRANSPOSED store, * rsqrt(max(rs[m]*cs[n], eps))
// EPI 2: fp32 direct store out[m][n]
// ---------------------------------------------------------------------------
template <int EPI>
__global__ __launch_bounds__(256, 2)
void mma_gemm(const bf16* __restrict__ Ah, const uint8_t* __restrict__ A8h,
              const uint8_t* __restrict__ A8l, size_t sA,
              const bf16* __restrict__ Bh, const uint8_t* __restrict__ B8h,
              const uint8_t* __restrict__ B8l, size_t sB,
              float* __restrict__ outF, bf16* __restrict__ oHi,
              uint8_t* __restrict__ o8h, uint8_t* __restrict__ o8l,
              const float* __restrict__ bias, const float* __restrict__ rs,
              const float* __restrict__ cs, float* __restrict__ partOut,
              float invs, float oSh, float oSl)
{
    extern __shared__ char smem[];
    const int tid  = threadIdx.x;
    const int lane = tid & 31, warp = tid >> 5;
    const int wm = (warp >> 2) * 64, wn = (warp & 3) * 32;
    const int bz = blockIdx.z;
    const int bm = blockIdx.y * 128, bn = blockIdx.x * 128;
    const uint32_t sbase = smem_to_u32(smem);

    const bf16*    pAh  = Ah  + (size_t)bz * sA + (size_t)bm * DIM;
    const uint8_t* pA8h = A8h + (size_t)bz * sA + (size_t)bm * DIM;
    const uint8_t* pA8l = A8l + (size_t)bz * sA + (size_t)bm * DIM;
    const bf16*    pBh  = Bh  + (size_t)bz * sB + (size_t)bn * DIM;
    const uint8_t* pB8h = B8h + (size_t)bz * sB + (size_t)bn * DIM;
    const uint8_t* pB8l = B8l + (size_t)bz * sB + (size_t)bn * DIM;

    // bf16 tile: 128 rows x 64B (2 rows / 128B smem row)
    auto load_bf16 = [&](uint32_t dst, const bf16* src, int kc) {
        #pragma unroll
        for (int j = 0; j < 2; j++) {
            int cid = tid + j * 256;           // 0..511
            int r = cid >> 2, c = cid & 3;
            uint32_t R = (uint32_t)(r >> 1);
            uint32_t q = (uint32_t)(((r & 1) * 4 + c)) ^ (R & 7);
            asm volatile("cp.async.cg.shared.global [%0], [%1], 16;"
                         :: "r"(dst + R * 128 + q * 16),
                            "l"(src + (size_t)r * DIM + kc + c * 8));
        }
    };
    // fp8 tile: 128 rows x 32B (4 rows / 128B smem row)
    auto load_f8 = [&](uint32_t dst, const uint8_t* src, int kc) {
        int r = tid >> 1, c = tid & 1;
        uint32_t R = (uint32_t)(r >> 2);
        uint32_t q = (uint32_t)(((r & 3) * 2 + c)) ^ (R & 7);
        asm volatile("cp.async.cg.shared.global [%0], [%1], 16;"
                     :: "r"(dst + R * 128 + q * 16),
                        "l"(src + (size_t)r * DIM + kc + c * 16));
    };
    auto load_stage = [&](int s, int kc) {
        uint32_t St = sbase + (uint32_t)s * STAGE_BYTES;
        load_bf16(St,          pAh,  kc);
        load_f8  (St + 8192,   pA8h, kc);
        load_f8  (St + 12288,  pA8l, kc);
        load_bf16(St + 16384,  pBh,  kc);
        load_f8  (St + 24576,  pB8h, kc);
        load_f8  (St + 28672,  pB8l, kc);
        asm volatile("cp.async.commit_group;" ::: "memory");
    };

    float acc[4][4][4];
    uint32_t acc8[4][4][2];
    #pragma unroll
    for (int a = 0; a < 4; a++)
        #pragma unroll
        for (int b = 0; b < 4; b++) {
            #pragma unroll
            for (int c = 0; c < 4; c++) acc[a][b][c] = 0.0f;
            acc8[a][b][0] = 0u; acc8[a][b][1] = 0u;
        }

    load_stage(0, 0);
    load_stage(1, 32);

    const int NCHUNK = 32;
    for (int i = 0; i < NCHUNK; i++) {
        if (i + 1 < NCHUNK) {
            asm volatile("cp.async.wait_group 1;" ::: "memory");
        } else {
            asm volatile("cp.async.wait_group 0;" ::: "memory");
        }
        __syncthreads();

        const uint32_t St   = sbase + (uint32_t)(i % NSTAGE) * STAGE_BYTES;
        const uint32_t Abh  = St;
        const uint32_t A8hS = St + 8192, A8lS = St + 12288;
        const uint32_t Bbh  = St + 16384;
        const uint32_t B8hS = St + 24576, B8lS = St + 28672;

        // ---- bf16 hi x hi -> acc ----
        #pragma unroll
        for (int kk = 0; kk < 2; kk++) {
            uint32_t bh[8];
            {
                const int rb = wn + ((lane >> 4) << 3) + (lane & 7);
                const uint32_t c = (uint32_t)(kk * 2 + ((lane >> 3) & 1));
                #pragma unroll
                for (int g = 0; g < 2; g++) {
                    int r = rb + g * 16;
                    uint32_t R = (uint32_t)(r >> 1);
                    uint32_t q = ((uint32_t)((r & 1) * 4) + c) ^ (R & 7);
                    LDSM4(&bh[g * 4], Bbh + R * 128 + q * 16);
                }
            }
            const int ra = wm + (lane & 15);
            const uint32_t ca = (uint32_t)(kk * 2 + (lane >> 4));
            #pragma unroll
            for (int im = 0; im < 4; im++) {
                uint32_t a[4];
                int r = ra + im * 16;
                uint32_t R = (uint32_t)(r >> 1);
                uint32_t q = ((uint32_t)((r & 1) * 4) + ca) ^ (R & 7);
                LDSM4(a, Abh + R * 128 + q * 16);
                #pragma unroll
                for (int jn = 0; jn < 4; jn++)
                    MMA(acc[im][jn], a, bh[2 * jn], bh[2 * jn + 1]);
            }
        }
        // ---- fp8 corrections -> acc8 (f16), same net scale both passes ----
        #pragma unroll
        for (int pass = 0; pass < 2; pass++) {
            const uint32_t Bsrc = (pass == 0) ? B8lS : B8hS;
            const uint32_t Asrc = (pass == 0) ? A8hS : A8lS;
            uint32_t bf8[8];
            {
                const int rb = wn + ((lane >> 4) << 3) + (lane & 7);
                const uint32_t c = (uint32_t)((lane >> 3) & 1);
                #pragma unroll
                for (int g = 0; g < 2; g++) {
                    int r = rb + g * 16;
                    uint32_t R = (uint32_t)(r >> 2);
                    uint32_t q = ((uint32_t)((r & 3) * 2) + c) ^ (R & 7);
                    LDSM4(&bf8[g * 4], Bsrc + R * 128 + q * 16);
                }
            }
            const int ra = wm + (lane & 15);
            const uint32_t ca = (uint32_t)(lane >> 4);
            #pragma unroll
            for (int im = 0; im < 4; im++) {
                uint32_t a[4];
                int r = ra + im * 16;
                uint32_t R = (uint32_t)(r >> 2);
                uint32_t q = ((uint32_t)((r & 3) * 2) + ca) ^ (R & 7);
                LDSM4(a, Asrc + R * 128 + q * 16);
                #pragma unroll
                for (int jn = 0; jn < 4; jn++)
                    MMA8H(acc8[im][jn], a, bf8[2 * jn], bf8[2 * jn + 1]);
            }
        }

        if (i + 2 < NCHUNK) load_stage((i + 2) % NSTAGE, (i + 2) * 32);
    }
    __syncthreads();

    // ---- epilogue: combine (+bias), stage through padded fp32 smem ----
    float* sfl = (float*)smem;                    // [128][129] = 66048 B
    #pragma unroll
    for (int im = 0; im < 4; im++) {
        float bv0 = 0.f, bv1 = 0.f;
        if (EPI == 0) {
            bv0 = bias[bm + wm + im * 16 + (lane >> 2)];
            bv1 = bias[bm + wm + im * 16 + (lane >> 2) + 8];
        }
        #pragma unroll
        for (int jn = 0; jn < 4; jn++) {
            int m  = wm + im * 16 + (lane >> 2);
            int nn = wn + jn * 8 + 2 * (lane & 3);
            float2 c01 = __half22float2(*(__half2*)&acc8[im][jn][0]);
            float2 c23 = __half22float2(*(__half2*)&acc8[im][jn][1]);
            sfl[m * 129 + nn]           = fmaf(c01.x, invs, acc[im][jn][0]) + bv0;
            sfl[m * 129 + nn + 1]       = fmaf(c01.y, invs, acc[im][jn][1]) + bv0;
            sfl[(m + 8) * 129 + nn]     = fmaf(c23.x, invs, acc[im][jn][2]) + bv1;
            sfl[(m + 8) * 129 + nn + 1] = fmaf(c23.y, invs, acc[im][jn][3]) + bv1;
        }
    }
    __syncthreads();

    const size_t obase = (size_t)bz * (size_t)(DIM * DIM);
    if (EPI == 0) {
        #pragma unroll 1
        for (int idx = tid; idx < 128 * 128; idx += 256) {
            int nn = idx >> 7, m = idx & 127;
            float v = sfl[m * 129 + nn];
            bf16 h = __float2bfloat16(v);
            size_t o = obase + (size_t)(bn + nn) * DIM + bm + m;
            oHi[o] = h;
            o8h[o] = to_e4m3(v * oSh);
            o8l[o] = to_e4m3((v - __bfloat162float(h)) * oSl);
        }
        // exact deterministic partial column norms over this CTA's 128 m
        float* sscr = (float*)(smem + 66304);     // [2][128]
        {
            int nn = tid & 127, mh = (tid >> 7) * 64;
            float ps = 0.0f;
            #pragma unroll 4
            for (int m = mh; m < mh + 64; m++) {
                float vv = sfl[m * 129 + nn];
                ps = fmaf(vv, vv, ps);
            }
            sscr[(tid >> 7) * 128 + nn] = ps;
        }
        __syncthreads();
        if (tid < 128)
            partOut[(size_t)(bm >> 7) * (NB * DIM) + (size_t)bz * DIM + bn + tid] =
                sscr[tid] + sscr[128 + tid];
    } else if (EPI == 1) {
        #pragma unroll 1
        for (int idx = tid; idx < 128 * 128; idx += 256) {
            int nn = idx >> 7, m = idx & 127;
            float v = sfl[m * 129 + nn];
            float sc = rsqrtf(fmaxf(rs[bz * DIM + bm + m] * cs[bz * DIM + bn + nn], EPSF));
            outF[obase + (size_t)(bn + nn) * DIM + bm + m] = v * sc;
        }
    } else {
        #pragma unroll 1
        for (int idx = tid; idx < 128 * 128; idx += 256) {
            int m = idx >> 7, nn = idx & 127;
            outF[obase + (size_t)(bm + m) * DIM + bn + nn] = sfl[m * 129 + nn];
        }
    }
}

// ---------------------------------------------------------------------------
// Elementwise kernels
// ---------------------------------------------------------------------------
__global__ __launch_bounds__(256)
void w_split(const float* __restrict__ Wk, const float* __restrict__ Wq)
{
    int i = blockIdx.x * 256 + threadIdx.x;
    float a = Wk[i];
    bf16 h = __float2bfloat16(a);
    g_Wk_h[i] = h; g_Wk_8h[i] = to_e4m3(a * SH_W);
    g_Wk_8l[i] = to_e4m3((a - __bfloat162float(h)) * SL_W);
    float b = Wq[i];
    h = __float2bfloat16(b);
    g_Wq_h[i] = h; g_Wq_8h[i] = to_e4m3(b * SH_W);
    g_Wq_8l[i] = to_e4m3((b - __bfloat162float(h)) * SL_W);
}

__global__ __launch_bounds__(256)
void xprep(const float* __restrict__ X)
{
    __shared__ float t[32][33];
    const int n = blockIdx.z, b0 = blockIdx.x * 32, d0 = blockIdx.y * 32;
    const int tx = threadIdx.x, ty = threadIdx.y;
    const size_t base = (size_t)n << 20;
    const float* Xn = X + base;
    #pragma unroll
    for (int r = 0; r < 4; r++) {
        int row = ty + r * 8;
        float v = Xn[(size_t)(d0 + row) * DIM + b0 + tx];
        t[row][tx] = v;
        bf16 h = __float2bfloat16(v);
        size_t o = base + (size_t)(d0 + row) * DIM + b0 + tx;
        g_X_h[o] = h; g_X_8h[o] = to_e4m3(v * SH_X);
        g_X_8l[o] = to_e4m3((v - __bfloat162float(h)) * SL_X);
    }
    __syncthreads();
    #pragma unroll
    for (int r = 0; r < 4; r++) {
        int row = ty + r * 8;
        float v = t[tx][row];
        bf16 h = __float2bfloat16(v);
        size_t o = base + (size_t)(b0 + row) * DIM + d0 + tx;
        g_XT_h[o] = h; g_XT_8h[o] = to_e4m3(v * SH_X);
        g_XT_8l[o] = to_e4m3((v - __bfloat162float(h)) * SL_X);
    }
}

__global__ __launch_bounds__(256)
void norms_red()
{
    int idx = blockIdx.x * 256 + threadIdx.x;
    float sk = 0.f, sq = 0.f;
    #pragma unroll
    for (int t = 0; t < 8; t++) {
        sk += g_partK[t * (NB * DIM) + idx];
        sq += g_partQ[t * (NB * DIM) + idx];
    }
    g_DK2[idx] = sk;
    g_DQ2[idx] = sq;
}

__global__ __launch_bounds__(256)
void softmax_k()
{
    const int row = blockIdx.x;
    const int tid = threadIdx.x;
    float* y = g_YT + ((size_t)row << 10);
    float v[4];
    #pragma unroll
    for (int j = 0; j < 4; j++) v[j] = y[tid + j * 256];
    float m = fmaxf(fmaxf(v[0], v[1]), fmaxf(v[2], v[3]));
    __shared__ float red[8];
    #pragma unroll
    for (int o = 16; o > 0; o >>= 1) m = fmaxf(m, __shfl_xor_sync(0xFFFFFFFFu, m, o));
    if ((tid & 31) == 0) red[tid >> 5] = m;
    __syncthreads();
    float mall = red[0];
    #pragma unroll
    for (int w = 1; w < 8; w++) mall = fmaxf(mall, red[w]);
    float s = 0.f;
    #pragma unroll
    for (int j = 0; j < 4; j++) { v[j] = __expf(v[j] - mall); s += v[j]; }
    #pragma unroll
    for (int o = 16; o > 0; o >>= 1) s += __shfl_xor_sync(0xFFFFFFFFu, s, o);
    __syncthreads();
    if ((tid & 31) == 0) red[tid >> 5] = s;
    __syncthreads();
    float st = 0.f;
    #pragma unroll
    for (int w = 0; w < 8; w++) st += red[w];
    const float inv = 1.0f / st;
    #pragma unroll
    for (int j = 0; j < 4; j++) {
        float p = v[j] * inv;
        bf16 h = __float2bfloat16(p);
        size_t o = ((size_t)row << 10) + tid + j * 256;
        g_SM_h[o] = h; g_SM_8h[o] = to_e4m3(p * SH_SM);
        g_SM_8l[o] = to_e4m3((p - __bfloat162float(h)) * SL_SM);
    }
}

// ---------------------------------------------------------------------------
extern "C" void kernel_launch(void* const* d_in, const int* in_sizes, int n_in,
                              void* d_out, int out_size)
{
    const float* X   = (const float*)d_in[0];
    const float* Wk  = (const float*)d_in[1];
    const float* Wq  = (const float*)d_in[2];
    const float* Wk0 = (const float*)d_in[3];
    const float* Wq0 = (const float*)d_in[4];
    float* Z = (float*)d_out;

    cudaFuncSetAttribute(mma_gemm<0>, cudaFuncAttributeMaxDynamicSharedMemorySize, SMEM_BYTES);
    cudaFuncSetAttribute(mma_gemm<1>, cudaFuncAttributeMaxDynamicSharedMemorySize, SMEM_BYTES);
    cudaFuncSetAttribute(mma_gemm<2>, cudaFuncAttributeMaxDynamicSharedMemorySize, SMEM_BYTES);

    bf16 *Wkh, *Wqh, *Xh, *XTh, *KTh, *QTh, *SMh;
    uint8_t *Wk8h, *Wk8l, *Wq8h, *Wq8l, *X8h, *X8l, *XT8h, *XT8l;
    uint8_t *KT8h, *KT8l, *QT8h, *QT8l, *SM8h, *SM8l;
    float *YT, *dk2, *dq2, *pK, *pQ;
    cudaGetSymbolAddress((void**)&Wkh,  g_Wk_h);   cudaGetSymbolAddress((void**)&Wk8h, g_Wk_8h);
    cudaGetSymbolAddress((void**)&Wk8l, g_Wk_8l);
    cudaGetSymbolAddress((void**)&Wqh,  g_Wq_h);   cudaGetSymbolAddress((void**)&Wq8h, g_Wq_8h);
    cudaGetSymbolAddress((void**)&Wq8l, g_Wq_8l);
    cudaGetSymbolAddress((void**)&Xh,   g_X_h);    cudaGetSymbolAddress((void**)&X8h,  g_X_8h);
    cudaGetSymbolAddress((void**)&X8l,  g_X_8l);
    cudaGetSymbolAddress((void**)&XTh,  g_XT_h);   cudaGetSymbolAddress((void**)&XT8h, g_XT_8h);
    cudaGetSymbolAddress((void**)&XT8l, g_XT_8l);
    cudaGetSymbolAddress((void**)&KTh,  g_KT_h);   cudaGetSymbolAddress((void**)&KT8h, g_KT_8h);
    cudaGetSymbolAddress((void**)&KT8l, g_KT_8l);
    cudaGetSymbolAddress((void**)&QTh,  g_QT_h);   cudaGetSymbolAddress((void**)&QT8h, g_QT_8h);
    cudaGetSymbolAddress((void**)&QT8l, g_QT_8l);
    cudaGetSymbolAddress((void**)&SMh,  g_SM_h);   cudaGetSymbolAddress((void**)&SM8h, g_SM_8h);
    cudaGetSymbolAddress((void**)&SM8l, g_SM_8l);
    cudaGetSymbolAddress((void**)&YT,   g_YT);
    cudaGetSymbolAddress((void**)&dk2,  g_DK2);    cudaGetSymbolAddress((void**)&dq2,  g_DQ2);
    cudaGetSymbolAddress((void**)&pK,   g_partK);  cudaGetSymbolAddress((void**)&pQ,   g_partQ);

    const size_t S = (size_t)DIM * DIM;
    dim3 gg(8, 8, NB);

    w_split<<<(DIM * DIM) / 256, 256>>>(Wk, Wq);
    xprep<<<dim3(32, 32, NB), dim3(32, 8)>>>(X);

    // KT = (Wk @ X)^T + Wk0 ; QT likewise; fused exact partial norms
    mma_gemm<0><<<gg, 256, SMEM_BYTES>>>(Wkh, Wk8h, Wk8l, 0, XTh, XT8h, XT8l, S,
                                         nullptr, KTh, KT8h, KT8l, Wk0, nullptr, nullptr, pK,
                                         INVS_KQ, SH_KQ, SL_KQ);
    mma_gemm<0><<<gg, 256, SMEM_BYTES>>>(Wqh, Wq8h, Wq8l, 0, XTh, XT8h, XT8l, S,
                                         nullptr, QTh, QT8h, QT8l, Wq0, nullptr, nullptr, pQ,
                                         INVS_KQ, SH_KQ, SL_KQ);
    norms_red<<<(NB * DIM) / 256, 256>>>();

    // YT[k,q] = (Q^T K)[q,k] * rsqrt(max(DQ2[q]*DK2[k], eps))
    mma_gemm<1><<<gg, 256, SMEM_BYTES>>>(QTh, QT8h, QT8l, S, KTh, KT8h, KT8l, S,
                                         YT, nullptr, nullptr, nullptr, nullptr, dq2, dk2, nullptr,
                                         INVS_Y, 0.f, 0.f);
    softmax_k<<<NB * DIM, 256>>>();

    // Z = X @ SM
    mma_gemm<2><<<gg, 256, SMEM_BYTES>>>(Xh, X8h, X8l, S, SMh, SM8h, SM8l, S,
                                         Z, nullptr, nullptr, nullptr, nullptr, nullptr, nullptr, nullptr,
                                         INVS_Z, 0.f, 0.f);
}

// round 13
// speedup vs baseline: 2.1647x; 2.1647x over previous
#include <cuda_runtime.h>
#include <cuda_fp16.h>
#include <stdint.h>
#include <math.h>

#define NB   32
#define DIM  1024
#define EPSF 1e-12f
#define SM_SCALE 128.0f
#define SM_DESCALE 0.0078125f

// ---------------- scratch (__device__ globals; no allocations) ----------------
__device__ __align__(128) __half g_Wk_h[DIM*DIM],  g_Wq_h[DIM*DIM];
__device__ __align__(128) __half g_X_h [NB*DIM*DIM];
__device__ __align__(128) __half g_XT_h[NB*DIM*DIM], g_XT_l[NB*DIM*DIM];
__device__ __align__(128) __half g_KT_h[NB*DIM*DIM], g_KT_l[NB*DIM*DIM];
__device__ __align__(128) __half g_QT_h[NB*DIM*DIM];
__device__ __align__(128) __half g_SM_h[NB*DIM*DIM], g_SM_l[NB*DIM*DIM];
__device__ __align__(128) float  g_YT[NB*DIM*DIM];
__device__ float g_partK[8*NB*DIM], g_partQ[8*NB*DIM];
__device__ float g_DK2[NB*DIM], g_DQ2[NB*DIM];

// ---------------- helpers ----------------
__device__ __forceinline__ uint32_t smem_to_u32(const void* p) {
    uint32_t a;
    asm("{ .reg .u64 t; cvta.to.shared.u64 t, %1; cvt.u32.u64 %0, t; }" : "=r"(a) : "l"(p));
    return a;
}

#define LDSM4(r, addr) \
    asm volatile("ldmatrix.sync.aligned.m8n8.x4.shared.b16 {%0,%1,%2,%3}, [%4];" \
        : "=r"((r)[0]), "=r"((r)[1]), "=r"((r)[2]), "=r"((r)[3]) : "r"(addr))

#define MMAF16(acc, a, b0, b1) \
    asm volatile("mma.sync.aligned.m16n8k16.row.col.f32.f16.f16.f32 " \
        "{%0,%1,%2,%3}, {%4,%5,%6,%7}, {%8,%9}, {%0,%1,%2,%3};" \
        : "+f"((acc)[0]), "+f"((acc)[1]), "+f"((acc)[2]), "+f"((acc)[3]) \
        : "r"((a)[0]), "r"((a)[1]), "r"((a)[2]), "r"((a)[3]), "r"(b0), "r"(b1))

// Stage: A-hi 8K + B-hi 8K + B-lo 8K = 24 KB (fp16 tiles, 64B rows, 2 rows/128B)
#define STAGE_BYTES 24576
#define NSTAGE 3
#define SMEM_BYTES (NSTAGE * STAGE_BYTES)   // 72 KB; epilogue fp32 [128][129]=66KB overlays

// ---------------------------------------------------------------------------
// Asymmetric-split fp16 GEMM: D[m,n] = sum_k A[m,k]*B[n,k], K-major operands.
// CTA 128x128, 8 warps (2m x 4n), warp tile 64x32, BK=32, 3-stage cp.async.
// 2 passes into ONE fp32 acc: Ahi*Bhi + Ahi*Blo. (Skipped Alo*B ~1.4e-4 rel.)
// EPI 0: fp16 hi/lo TRANSPOSED store out[n][m], +bias, + exact deterministic
//        per-CTA partial column norms.
// EPI 1: fp32 TRANSPOSED store, * rsqrt(max(rs[m]*cs[n], eps))
// EPI 2: fp32 direct store out[m][n] * outScale
// ---------------------------------------------------------------------------
template <int EPI>
__global__ __launch_bounds__(256, 2)
void mma_gemm(const __half* __restrict__ Ah, size_t sA,
              const __half* __restrict__ Bh, const __half* __restrict__ Bl, size_t sB,
              float* __restrict__ outF, __half* __restrict__ oHi, __half* __restrict__ oLo,
              const float* __restrict__ bias, const float* __restrict__ rs,
              const float* __restrict__ cs, float* __restrict__ partOut,
              float outScale)
{
    extern __shared__ char smem[];
    const int tid  = threadIdx.x;
    const int lane = tid & 31, warp = tid >> 5;
    const int wm = (warp >> 2) * 64, wn = (warp & 3) * 32;
    const int bz = blockIdx.z;
    const int bm = blockIdx.y * 128, bn = blockIdx.x * 128;
    const uint32_t sbase = smem_to_u32(smem);

    const __half* pAh = Ah + (size_t)bz * sA + (size_t)bm * DIM;
    const __half* pBh = Bh + (size_t)bz * sB + (size_t)bn * DIM;
    const __half* pBl = Bl + (size_t)bz * sB + (size_t)bn * DIM;

    // fp16 tile: 128 rows x 64B; 2 rows per 128B smem row, swizzle q=((r&1)*4+c)^(R&7)
    auto load_tile = [&](uint32_t dst, const __half* src, int kc) {
        #pragma unroll
        for (int j = 0; j < 2; j++) {
            int cid = tid + j * 256;           // 0..511
            int r = cid >> 2, c = cid & 3;
            uint32_t R = (uint32_t)(r >> 1);
            uint32_t q = (uint32_t)(((r & 1) * 4 + c)) ^ (R & 7);
            asm volatile("cp.async.cg.shared.global [%0], [%1], 16;"
                         :: "r"(dst + R * 128 + q * 16),
                            "l"(src + (size_t)r * DIM + kc + c * 8));
        }
    };
    auto load_stage = [&](int s, int kc) {
        uint32_t St = sbase + (uint32_t)s * STAGE_BYTES;
        load_tile(St,          pAh, kc);
        load_tile(St + 8192,   pBh, kc);
        load_tile(St + 16384,  pBl, kc);
        asm volatile("cp.async.commit_group;" ::: "memory");
    };

    float acc[4][4][4];
    #pragma unroll
    for (int a = 0; a < 4; a++)
        #pragma unroll
        for (int b = 0; b < 4; b++)
            #pragma unroll
            for (int c = 0; c < 4; c++)
                acc[a][b][c] = 0.0f;

    load_stage(0, 0);
    load_stage(1, 32);

    const int NCHUNK = 32;
    for (int i = 0; i < NCHUNK; i++) {
        if (i + 1 < NCHUNK) {
            asm volatile("cp.async.wait_group 1;" ::: "memory");
        } else {
            asm volatile("cp.async.wait_group 0;" ::: "memory");
        }
        __syncthreads();   // stage i visible; all warps done with chunk i-1

        const uint32_t Ab = sbase + (uint32_t)(i % NSTAGE) * STAGE_BYTES;
        const uint32_t Bhb = Ab + 8192, Blb = Ab + 16384;

        #pragma unroll
        for (int kk = 0; kk < 2; kk++) {
            uint32_t bh[8], bl[8];
            {
                const int rb = wn + ((lane >> 4) << 3) + (lane & 7);
                const uint32_t c = (uint32_t)(kk * 2 + ((lane >> 3) & 1));
                #pragma unroll
                for (int g = 0; g < 2; g++) {
                    int r = rb + g * 16;
                    uint32_t R = (uint32_t)(r >> 1);
                    uint32_t q = ((uint32_t)((r & 1) * 4) + c) ^ (R & 7);
                    LDSM4(&bh[g * 4], Bhb + R * 128 + q * 16);
                    LDSM4(&bl[g * 4], Blb + R * 128 + q * 16);
                }
            }
            const int ra = wm + (lane & 15);
            const uint32_t ca = (uint32_t)(kk * 2 + (lane >> 4));
            uint32_t af[2][4];
            {
                int r = ra;
                uint32_t R = (uint32_t)(r >> 1);
                uint32_t q = ((uint32_t)((r & 1) * 4) + ca) ^ (R & 7);
                LDSM4(af[0], Ab + R * 128 + q * 16);
            }
            #pragma unroll
            for (int im = 0; im < 4; im++) {
                const int cur = im & 1, nxt = cur ^ 1;
                if (im < 3) {
                    int r = ra + (im + 1) * 16;
                    uint32_t R = (uint32_t)(r >> 1);
                    uint32_t q = ((uint32_t)((r & 1) * 4) + ca) ^ (R & 7);
                    LDSM4(af[nxt], Ab + R * 128 + q * 16);
                }
                #pragma unroll
                for (int jn = 0; jn < 4; jn++)
                    MMAF16(acc[im][jn], af[cur], bh[2 * jn], bh[2 * jn + 1]);
                #pragma unroll
                for (int jn = 0; jn < 4; jn++)
                    MMAF16(acc[im][jn], af[cur], bl[2 * jn], bl[2 * jn + 1]);
            }
        }

        // issue next loads AFTER compute (single-barrier pipeline, stage (i+2)%3)
        if (i + 2 < NCHUNK)
            load_stage((i + 2) % NSTAGE, (i + 2) * 32);
    }
    __syncthreads();

    // ---- epilogue: (+bias), stage through padded fp32 smem [128][129] ----
    float* sfl = (float*)smem;
    #pragma unroll
    for (int im = 0; im < 4; im++) {
        float bv0 = 0.f, bv1 = 0.f;
        if (EPI == 0) {
            bv0 = bias[bm + wm + im * 16 + (lane >> 2)];
            bv1 = bias[bm + wm + im * 16 + (lane >> 2) + 8];
        }
        #pragma unroll
        for (int jn = 0; jn < 4; jn++) {
            int m  = wm + im * 16 + (lane >> 2);
            int nn = wn + jn * 8 + 2 * (lane & 3);
            sfl[m * 129 + nn]           = acc[im][jn][0] + bv0;
            sfl[m * 129 + nn + 1]       = acc[im][jn][1] + bv0;
            sfl[(m + 8) * 129 + nn]     = acc[im][jn][2] + bv1;
            sfl[(m + 8) * 129 + nn + 1] = acc[im][jn][3] + bv1;
        }
    }
    __syncthreads();

    const size_t obase = (size_t)bz * (size_t)(DIM * DIM);
    if (EPI == 0) {
        #pragma unroll 1
        for (int idx = tid; idx < 128 * 128; idx += 256) {
            int nn = idx >> 7, m = idx & 127;
            float v = sfl[m * 129 + nn];
            __half h = __float2half(v);
            size_t o = obase + (size_t)(bn + nn) * DIM + bm + m;
            oHi[o] = h;
            if (oLo) oLo[o] = __float2half(v - __half2float(h));
        }
        // exact deterministic partial column norms over this CTA's 128 m rows
        float* sscr = (float*)(smem + 66304);     // [2][128]
        {
            int nn = tid & 127, mh = (tid >> 7) * 64;
            float ps = 0.0f;
            #pragma unroll 4
            for (int m = mh; m < mh + 64; m++) {
                float vv = sfl[m * 129 + nn];
                ps = fmaf(vv, vv, ps);
            }
            sscr[(tid >> 7) * 128 + nn] = ps;
        }
        __syncthreads();
        if (tid < 128)
            partOut[(size_t)(bm >> 7) * (NB * DIM) + (size_t)bz * DIM + bn + tid] =
                sscr[tid] + sscr[128 + tid];
    } else if (EPI == 1) {
        #pragma unroll 1
        for (int idx = tid; idx < 128 * 128; idx += 256) {
            int nn = idx >> 7, m = idx & 127;
            float v = sfl[m * 129 + nn];
            float sc = rsqrtf(fmaxf(rs[bz * DIM + bm + m] * cs[bz * DIM + bn + nn], EPSF));
            outF[obase + (size_t)(bn + nn) * DIM + bm + m] = v * sc;
        }
    } else {
        #pragma unroll 1
        for (int idx = tid; idx < 128 * 128; idx += 256) {
            int m = idx >> 7, nn = idx & 127;
            outF[obase + (size_t)(bm + m) * DIM + bn + nn] = sfl[m * 129 + nn] * outScale;
        }
    }
}

// ---------------------------------------------------------------------------
// Elementwise kernels
// ---------------------------------------------------------------------------
__global__ __launch_bounds__(256)
void w_split(const float* __restrict__ Wk, const float* __restrict__ Wq)
{
    int i = blockIdx.x * 256 + threadIdx.x;
    g_Wk_h[i] = __float2half(Wk[i]);
    g_Wq_h[i] = __float2half(Wq[i]);
}

// X[n][d][b] -> X_h (same layout, fp16 hi) + XT_h/XT_l [n][b][d]
__global__ __launch_bounds__(256)
void xprep(const float* __restrict__ X)
{
    __shared__ float t[32][33];
    const int n = blockIdx.z, b0 = blockIdx.x * 32, d0 = blockIdx.y * 32;
    const int tx = threadIdx.x, ty = threadIdx.y;
    const size_t base = (size_t)n << 20;
    const float* Xn = X + base;
    #pragma unroll
    for (int r = 0; r < 4; r++) {
        int row = ty + r * 8;
        float v = Xn[(size_t)(d0 + row) * DIM + b0 + tx];
        t[row][tx] = v;
        g_X_h[base + (size_t)(d0 + row) * DIM + b0 + tx] = __float2half(v);
    }
    __syncthreads();
    #pragma unroll
    for (int r = 0; r < 4; r++) {
        int row = ty + r * 8;
        float v = t[tx][row];                    // = X[d0+tx][b0+row]
        __half h = __float2half(v);
        size_t o = base + (size_t)(b0 + row) * DIM + d0 + tx;
        g_XT_h[o] = h;
        g_XT_l[o] = __float2half(v - __half2float(h));
    }
}

// Reduce 8 deterministic partials -> DK2/DQ2
__global__ __launch_bounds__(256)
void norms_red()
{
    int idx = blockIdx.x * 256 + threadIdx.x;
    float sk = 0.f, sq = 0.f;
    #pragma unroll
    for (int t = 0; t < 8; t++) {
        sk += g_partK[t * (NB * DIM) + idx];
        sq += g_partQ[t * (NB * DIM) + idx];
    }
    g_DK2[idx] = sk;
    g_DQ2[idx] = sq;
}

// Row softmax of YT -> SM (scaled x128) fp16 hi/lo
__global__ __launch_bounds__(256)
void softmax_k()
{
    const int row = blockIdx.x;
    const int tid = threadIdx.x;
    float* y = g_YT + ((size_t)row << 10);
    float v[4];
    #pragma unroll
    for (int j = 0; j < 4; j++) v[j] = y[tid + j * 256];
    float m = fmaxf(fmaxf(v[0], v[1]), fmaxf(v[2], v[3]));
    __shared__ float red[8];
    #pragma unroll
    for (int o = 16; o > 0; o >>= 1) m = fmaxf(m, __shfl_xor_sync(0xFFFFFFFFu, m, o));
    if ((tid & 31) == 0) red[tid >> 5] = m;
    __syncthreads();
    float mall = red[0];
    #pragma unroll
    for (int w = 1; w < 8; w++) mall = fmaxf(mall, red[w]);
    float s = 0.f;
    #pragma unroll
    for (int j = 0; j < 4; j++) { v[j] = __expf(v[j] - mall); s += v[j]; }
    #pragma unroll
    for (int o = 16; o > 0; o >>= 1) s += __shfl_xor_sync(0xFFFFFFFFu, s, o);
    __syncthreads();
    if ((tid & 31) == 0) red[tid >> 5] = s;
    __syncthreads();
    float st = 0.f;
    #pragma unroll
    for (int w = 0; w < 8; w++) st += red[w];
    const float inv = SM_SCALE / st;
    #pragma unroll
    for (int j = 0; j < 4; j++) {
        float p = v[j] * inv;                    // scaled prob
        __half h = __float2half(p);
        size_t o = ((size_t)row << 10) + tid + j * 256;
        g_SM_h[o] = h;
        g_SM_l[o] = __float2half(p - __half2float(h));
    }
}

// ---------------------------------------------------------------------------
extern "C" void kernel_launch(void* const* d_in, const int* in_sizes, int n_in,
                              void* d_out, int out_size)
{
    const float* X   = (const float*)d_in[0];
    const float* Wk  = (const float*)d_in[1];
    const float* Wq  = (const float*)d_in[2];
    const float* Wk0 = (const float*)d_in[3];
    const float* Wq0 = (const float*)d_in[4];
    float* Z = (float*)d_out;

    cudaFuncSetAttribute(mma_gemm<0>, cudaFuncAttributeMaxDynamicSharedMemorySize, SMEM_BYTES);
    cudaFuncSetAttribute(mma_gemm<1>, cudaFuncAttributeMaxDynamicSharedMemorySize, SMEM_BYTES);
    cudaFuncSetAttribute(mma_gemm<2>, cudaFuncAttributeMaxDynamicSharedMemorySize, SMEM_BYTES);

    __half *Wkh, *Wqh, *Xh, *XTh, *XTl, *KTh, *KTl, *QTh, *SMh, *SMl;
    float *YT, *dk2, *dq2, *pK, *pQ;
    cudaGetSymbolAddress((void**)&Wkh, g_Wk_h);   cudaGetSymbolAddress((void**)&Wqh, g_Wq_h);
    cudaGetSymbolAddress((void**)&Xh,  g_X_h);
    cudaGetSymbolAddress((void**)&XTh, g_XT_h);   cudaGetSymbolAddress((void**)&XTl, g_XT_l);
    cudaGetSymbolAddress((void**)&KTh, g_KT_h);   cudaGetSymbolAddress((void**)&KTl, g_KT_l);
    cudaGetSymbolAddress((void**)&QTh, g_QT_h);
    cudaGetSymbolAddress((void**)&SMh, g_SM_h);   cudaGetSymbolAddress((void**)&SMl, g_SM_l);
    cudaGetSymbolAddress((void**)&YT,  g_YT);
    cudaGetSymbolAddress((void**)&dk2, g_DK2);    cudaGetSymbolAddress((void**)&dq2, g_DQ2);
    cudaGetSymbolAddress((void**)&pK,  g_partK);  cudaGetSymbolAddress((void**)&pQ,  g_partQ);

    const size_t S = (size_t)DIM * DIM;
    dim3 gg(8, 8, NB);

    w_split<<<(DIM * DIM) / 256, 256>>>(Wk, Wq);
    xprep<<<dim3(32, 32, NB), dim3(32, 8)>>>(X);

    // KT[b,c] = (Wk @ X)^T + Wk0 (fp16 hi/lo); QT hi only; fused exact norms
    mma_gemm<0><<<gg, 256, SMEM_BYTES>>>(Wkh, 0, XTh, XTl, S,
                                         nullptr, KTh, KTl, Wk0, nullptr, nullptr, pK, 1.0f);
    mma_gemm<0><<<gg, 256, SMEM_BYTES>>>(Wqh, 0, XTh, XTl, S,
                                         nullptr, QTh, nullptr, Wq0, nullptr, nullptr, pQ, 1.0f);
    norms_red<<<(NB * DIM) / 256, 256>>>();

    // YT[k,q] = (Q^T K)[q,k] * rsqrt(max(DQ2[q]*DK2[k], eps))
    mma_gemm<1><<<gg, 256, SMEM_BYTES>>>(QTh, S, KTh, KTl, S,
                                         YT, nullptr, nullptr, nullptr, dq2, dk2, nullptr, 1.0f);
    softmax_k<<<NB * DIM, 256>>>();

    // Z = X @ (SM*128) / 128
    mma_gemm<2><<<gg, 256, SMEM_BYTES>>>(Xh, S, SMh, SMl, S,
                                         Z, nullptr, nullptr, nullptr, nullptr, nullptr, nullptr,
                                         SM_DESCALE);
}

// round 15
// speedup vs baseline: 3.6608x; 1.6911x over previous
#include <cuda_runtime.h>
#include <cuda_fp16.h>
#include <stdint.h>
#include <math.h>

#define NB   32
#define DIM  1024
#define EPSF 1e-12f
#define SM_SCALE 128.0f
#define SM_DESCALE 0.0078125f

// ---------------- scratch (__device__ globals; no allocations) ----------------
__device__ __align__(128) __half g_Wk_h[DIM*DIM],  g_Wq_h[DIM*DIM];
__device__ __align__(128) __half g_X_h [NB*DIM*DIM];
__device__ __align__(128) __half g_XT_h[NB*DIM*DIM];
__device__ __align__(128) __half g_KT_h[NB*DIM*DIM];
__device__ __align__(128) __half g_QT_h[NB*DIM*DIM];
__device__ __align__(128) __half g_SM_h[NB*DIM*DIM];
__device__ __align__(128) float  g_YT[NB*DIM*DIM];
__device__ float g_partK[8*NB*DIM], g_partQ[8*NB*DIM];
__device__ float g_DK2[NB*DIM], g_DQ2[NB*DIM];

// ---------------- helpers ----------------
__device__ __forceinline__ uint32_t smem_to_u32(const void* p) {
    uint32_t a;
    asm("{ .reg .u64 t; cvta.to.shared.u64 t, %1; cvt.u32.u64 %0, t; }" : "=r"(a) : "l"(p));
    return a;
}

#define LDSM4(r, addr) \
    asm volatile("ldmatrix.sync.aligned.m8n8.x4.shared.b16 {%0,%1,%2,%3}, [%4];" \
        : "=r"((r)[0]), "=r"((r)[1]), "=r"((r)[2]), "=r"((r)[3]) : "r"(addr))

#define MMAF16(acc, a, b0, b1) \
    asm volatile("mma.sync.aligned.m16n8k16.row.col.f32.f16.f16.f32 " \
        "{%0,%1,%2,%3}, {%4,%5,%6,%7}, {%8,%9}, {%0,%1,%2,%3};" \
        : "+f"((acc)[0]), "+f"((acc)[1]), "+f"((acc)[2]), "+f"((acc)[3]) \
        : "r"((a)[0]), "r"((a)[1]), "r"((a)[2]), "r"((a)[3]), "r"(b0), "r"(b1))

// Stage (BK=64): A 16K + B 16K = 32 KB; fp16 tiles, full 128B rows, q = c^(r&7)
#define STAGE_BYTES 32768
#define NSTAGE 3
#define SMEM_BYTES (NSTAGE * STAGE_BYTES)   // 96 KB; epilogue fp32 [128][129]=66KB overlays

// ---------------------------------------------------------------------------
// Single-pass fp16 GEMM: D[m,n] = sum_k Ah[m,k]*Bh[n,k], K-major operands.
// CTA 128x128, 8 warps (2m x 4n), warp tile 64x32, BK=64, 3-stage cp.async,
// single barrier per chunk, A-fragment double buffering. 2 CTAs/SM.
// EPI 0: fp16 TRANSPOSED store out[n][m], +bias, + exact deterministic
//        per-CTA partial column norms (from fp32 accumulators).
// EPI 1: fp32 TRANSPOSED store, * rsqrt(max(rs[m]*cs[n], eps))
// EPI 2: fp32 direct store out[m][n] * outScale
// ---------------------------------------------------------------------------
template <int EPI>
__global__ __launch_bounds__(256, 2)
void mma_gemm(const __half* __restrict__ Ah, size_t sA,
              const __half* __restrict__ Bh, size_t sB,
              float* __restrict__ outF, __half* __restrict__ oHi,
              const float* __restrict__ bias, const float* __restrict__ rs,
              const float* __restrict__ cs, float* __restrict__ partOut,
              float outScale)
{
    extern __shared__ char smem[];
    const int tid  = threadIdx.x;
    const int lane = tid & 31, warp = tid >> 5;
    const int wm = (warp >> 2) * 64, wn = (warp & 3) * 32;
    const int bz = blockIdx.z;
    const int bm = blockIdx.y * 128, bn = blockIdx.x * 128;
    const uint32_t sbase = smem_to_u32(smem);

    const __half* pAh = Ah + (size_t)bz * sA + (size_t)bm * DIM;
    const __half* pBh = Bh + (size_t)bz * sB + (size_t)bn * DIM;

    // tile: 128 rows x 128B (64 fp16); 16B chunk c (0..7) at q = c ^ (r&7)
    auto load_tile = [&](uint32_t dst, const __half* src, int kc) {
        #pragma unroll
        for (int j = 0; j < 4; j++) {
            int cid = tid + j * 256;           // 0..1023
            int r = cid >> 3, c = cid & 7;
            uint32_t q = (uint32_t)(c ^ (r & 7));
            asm volatile("cp.async.cg.shared.global [%0], [%1], 16;"
                         :: "r"(dst + (uint32_t)(r * 128) + q * 16),
                            "l"(src + (size_t)r * DIM + kc + c * 8));
        }
    };
    auto load_stage = [&](int s, int kc) {
        uint32_t St = sbase + (uint32_t)s * STAGE_BYTES;
        load_tile(St,          pAh, kc);
        load_tile(St + 16384,  pBh, kc);
        asm volatile("cp.async.commit_group;" ::: "memory");
    };

    float acc[4][4][4];
    #pragma unroll
    for (int a = 0; a < 4; a++)
        #pragma unroll
        for (int b = 0; b < 4; b++)
            #pragma unroll
            for (int c = 0; c < 4; c++)
                acc[a][b][c] = 0.0f;

    load_stage(0, 0);
    load_stage(1, 64);

    const int NCHUNK = 16;   // K / 64
    for (int i = 0; i < NCHUNK; i++) {
        if (i + 1 < NCHUNK) {
            asm volatile("cp.async.wait_group 1;" ::: "memory");
        } else {
            asm volatile("cp.async.wait_group 0;" ::: "memory");
        }
        __syncthreads();   // stage i visible; all warps done with chunk i-1

        const uint32_t Ab = sbase + (uint32_t)(i % NSTAGE) * STAGE_BYTES;
        const uint32_t Bb = Ab + 16384;

        #pragma unroll
        for (int kk = 0; kk < 4; kk++) {
            uint32_t bh[8];
            {
                const int rb = wn + ((lane >> 4) << 3) + (lane & 7);
                const uint32_t c = (uint32_t)(kk * 2 + ((lane >> 3) & 1));
                #pragma unroll
                for (int g = 0; g < 2; g++) {
                    int r = rb + g * 16;
                    uint32_t q = c ^ (uint32_t)(r & 7);
                    LDSM4(&bh[g * 4], Bb + (uint32_t)(r * 128) + q * 16);
                }
            }
            const int ra = wm + (lane & 15);
            const uint32_t ca = (uint32_t)(kk * 2 + (lane >> 4));
            uint32_t af[2][4];
            {
                int r = ra;
                uint32_t q = ca ^ (uint32_t)(r & 7);
                LDSM4(af[0], Ab + (uint32_t)(r * 128) + q * 16);
            }
            #pragma unroll
            for (int im = 0; im < 4; im++) {
                const int cur = im & 1, nxt = cur ^ 1;
                if (im < 3) {
                    int r = ra + (im + 1) * 16;
                    uint32_t q = ca ^ (uint32_t)(r & 7);
                    LDSM4(af[nxt], Ab + (uint32_t)(r * 128) + q * 16);
                }
                #pragma unroll
                for (int jn = 0; jn < 4; jn++)
                    MMAF16(acc[im][jn], af[cur], bh[2 * jn], bh[2 * jn + 1]);
            }
        }

        // issue next loads AFTER compute (single-barrier pipeline, stage (i+2)%3)
        if (i + 2 < NCHUNK)
            load_stage((i + 2) % NSTAGE, (i + 2) * 64);
    }
    __syncthreads();

    // ---- epilogue: (+bias), stage through padded fp32 smem [128][129] ----
    float* sfl = (float*)smem;
    #pragma unroll
    for (int im = 0; im < 4; im++) {
        float bv0 = 0.f, bv1 = 0.f;
        if (EPI == 0) {
            bv0 = bias[bm + wm + im * 16 + (lane >> 2)];
            bv1 = bias[bm + wm + im * 16 + (lane >> 2) + 8];
        }
        #pragma unroll
        for (int jn = 0; jn < 4; jn++) {
            int m  = wm + im * 16 + (lane >> 2);
            int nn = wn + jn * 8 + 2 * (lane & 3);
            sfl[m * 129 + nn]           = acc[im][jn][0] + bv0;
            sfl[m * 129 + nn + 1]       = acc[im][jn][1] + bv0;
            sfl[(m + 8) * 129 + nn]     = acc[im][jn][2] + bv1;
            sfl[(m + 8) * 129 + nn + 1] = acc[im][jn][3] + bv1;
        }
    }
    __syncthreads();

    const size_t obase = (size_t)bz * (size_t)(DIM * DIM);
    if (EPI == 0) {
        #pragma unroll 1
        for (int idx = tid; idx < 128 * 128; idx += 256) {
            int nn = idx >> 7, m = idx & 127;
            float v = sfl[m * 129 + nn];
            oHi[obase + (size_t)(bn + nn) * DIM + bm + m] = __float2half(v);
        }
        // exact deterministic partial column norms over this CTA's 128 m rows
        float* sscr = (float*)(smem + 66304);     // [2][128]
        {
            int nn = tid & 127, mh = (tid >> 7) * 64;
            float ps = 0.0f;
            #pragma unroll 4
            for (int m = mh; m < mh + 64; m++) {
                float vv = sfl[m * 129 + nn];
                ps = fmaf(vv, vv, ps);
            }
            sscr[(tid >> 7) * 128 + nn] = ps;
        }
        __syncthreads();
        if (tid < 128)
            partOut[(size_t)(bm >> 7) * (NB * DIM) + (size_t)bz * DIM + bn + tid] =
                sscr[tid] + sscr[128 + tid];
    } else if (EPI == 1) {
        #pragma unroll 1
        for (int idx = tid; idx < 128 * 128; idx += 256) {
            int nn = idx >> 7, m = idx & 127;
            float v = sfl[m * 129 + nn];
            float sc = rsqrtf(fmaxf(rs[bz * DIM + bm + m] * cs[bz * DIM + bn + nn], EPSF));
            outF[obase + (size_t)(bn + nn) * DIM + bm + m] = v * sc;
        }
    } else {
        #pragma unroll 1
        for (int idx = tid; idx < 128 * 128; idx += 256) {
            int m = idx >> 7, nn = idx & 127;
            outF[obase + (size_t)(bm + m) * DIM + bn + nn] = sfl[m * 129 + nn] * outScale;
        }
    }
}

// ---------------------------------------------------------------------------
// Elementwise kernels
// ---------------------------------------------------------------------------
__global__ __launch_bounds__(256)
void w_split(const float* __restrict__ Wk, const float* __restrict__ Wq)
{
    int i = blockIdx.x * 256 + threadIdx.x;
    g_Wk_h[i] = __float2half(Wk[i]);
    g_Wq_h[i] = __float2half(Wq[i]);
}

// X[n][d][b] -> X_h (same layout) + XT_h [n][b][d]
__global__ __launch_bounds__(256)
void xprep(const float* __restrict__ X)
{
    __shared__ float t[32][33];
    const int n = blockIdx.z, b0 = blockIdx.x * 32, d0 = blockIdx.y * 32;
    const int tx = threadIdx.x, ty = threadIdx.y;
    const size_t base = (size_t)n << 20;
    const float* Xn = X + base;
    #pragma unroll
    for (int r = 0; r < 4; r++) {
        int row = ty + r * 8;
        float v = Xn[(size_t)(d0 + row) * DIM + b0 + tx];
        t[row][tx] = v;
        g_X_h[base + (size_t)(d0 + row) * DIM + b0 + tx] = __float2half(v);
    }
    __syncthreads();
    #pragma unroll
    for (int r = 0; r < 4; r++) {
        int row = ty + r * 8;
        g_XT_h[base + (size_t)(b0 + row) * DIM + d0 + tx] = __float2half(t[tx][row]);
    }
}

// Reduce 8 deterministic partials -> DK2/DQ2
__global__ __launch_bounds__(256)
void norms_red()
{
    int idx = blockIdx.x * 256 + threadIdx.x;
    float sk = 0.f, sq = 0.f;
    #pragma unroll
    for (int t = 0; t < 8; t++) {
        sk += g_partK[t * (NB * DIM) + idx];
        sq += g_partQ[t * (NB * DIM) + idx];
    }
    g_DK2[idx] = sk;
    g_DQ2[idx] = sq;
}

// Row softmax of YT -> SM (scaled x128) fp16
__global__ __launch_bounds__(256)
void softmax_k()
{
    const int row = blockIdx.x;
    const int tid = threadIdx.x;
    float* y = g_YT + ((size_t)row << 10);
    float v[4];
    #pragma unroll
    for (int j = 0; j < 4; j++) v[j] = y[tid + j * 256];
    float m = fmaxf(fmaxf(v[0], v[1]), fmaxf(v[2], v[3]));
    __shared__ float red[8];
    #pragma unroll
    for (int o = 16; o > 0; o >>= 1) m = fmaxf(m, __shfl_xor_sync(0xFFFFFFFFu, m, o));
    if ((tid & 31) == 0) red[tid >> 5] = m;
    __syncthreads();
    float mall = red[0];
    #pragma unroll
    for (int w = 1; w < 8; w++) mall = fmaxf(mall, red[w]);
    float s = 0.f;
    #pragma unroll
    for (int j = 0; j < 4; j++) { v[j] = __expf(v[j] - mall); s += v[j]; }
    #pragma unroll
    for (int o = 16; o > 0; o >>= 1) s += __shfl_xor_sync(0xFFFFFFFFu, s, o);
    __syncthreads();
    if ((tid & 31) == 0) red[tid >> 5] = s;
    __syncthreads();
    float st = 0.f;
    #pragma unroll
    for (int w = 0; w < 8; w++) st += red[w];
    const float inv = SM_SCALE / st;
    #pragma unroll
    for (int j = 0; j < 4; j++)
        g_SM_h[((size_t)row << 10) + tid + j * 256] = __float2half(v[j] * inv);
}

// ---------------------------------------------------------------------------
extern "C" void kernel_launch(void* const* d_in, const int* in_sizes, int n_in,
                              void* d_out, int out_size)
{
    const float* X   = (const float*)d_in[0];
    const float* Wk  = (const float*)d_in[1];
    const float* Wq  = (const float*)d_in[2];
    const float* Wk0 = (const float*)d_in[3];
    const float* Wq0 = (const float*)d_in[4];
    float* Z = (float*)d_out;

    cudaFuncSetAttribute(mma_gemm<0>, cudaFuncAttributeMaxDynamicSharedMemorySize, SMEM_BYTES);
    cudaFuncSetAttribute(mma_gemm<1>, cudaFuncAttributeMaxDynamicSharedMemorySize, SMEM_BYTES);
    cudaFuncSetAttribute(mma_gemm<2>, cudaFuncAttributeMaxDynamicSharedMemorySize, SMEM_BYTES);

    __half *Wkh, *Wqh, *Xh, *XTh, *KTh, *QTh, *SMh;
    float *YT, *dk2, *dq2, *pK, *pQ;
    cudaGetSymbolAddress((void**)&Wkh, g_Wk_h);   cudaGetSymbolAddress((void**)&Wqh, g_Wq_h);
    cudaGetSymbolAddress((void**)&Xh,  g_X_h);    cudaGetSymbolAddress((void**)&XTh, g_XT_h);
    cudaGetSymbolAddress((void**)&KTh, g_KT_h);   cudaGetSymbolAddress((void**)&QTh, g_QT_h);
    cudaGetSymbolAddress((void**)&SMh, g_SM_h);
    cudaGetSymbolAddress((void**)&YT,  g_YT);
    cudaGetSymbolAddress((void**)&dk2, g_DK2);    cudaGetSymbolAddress((void**)&dq2, g_DQ2);
    cudaGetSymbolAddress((void**)&pK,  g_partK);  cudaGetSymbolAddress((void**)&pQ,  g_partQ);

    const size_t S = (size_t)DIM * DIM;
    dim3 gg(8, 8, NB);

    w_split<<<(DIM * DIM) / 256, 256>>>(Wk, Wq);
    xprep<<<dim3(32, 32, NB), dim3(32, 8)>>>(X);

    // KT[b,c] = (Wk @ X)^T + Wk0 ; QT likewise; fused exact partial norms
    mma_gemm<0><<<gg, 256, SMEM_BYTES>>>(Wkh, 0, XTh, S,
                                         nullptr, KTh, Wk0, nullptr, nullptr, pK, 1.0f);
    mma_gemm<0><<<gg, 256, SMEM_BYTES>>>(Wqh, 0, XTh, S,
                                         nullptr, QTh, Wq0, nullptr, nullptr, pQ, 1.0f);
    norms_red<<<(NB * DIM) / 256, 256>>>();

    // YT[k,q] = (Q^T K)[q,k] * rsqrt(max(DQ2[q]*DK2[k], eps))
    mma_gemm<1><<<gg, 256, SMEM_BYTES>>>(QTh, S, KTh, S,
                                         YT, nullptr, nullptr, dq2, dk2, nullptr, 1.0f);
    softmax_k<<<NB * DIM, 256>>>();

    // Z = X @ (SM*128) / 128
    mma_gemm<2><<<gg, 256, SMEM_BYTES>>>(Xh, S, SMh, S,
                                         Z, nullptr, nullptr, nullptr, nullptr, nullptr,
                                         SM_DESCALE);
}